// round 11
// baseline (speedup 1.0000x reference)
#include <cuda_runtime.h>
#include <cuda_fp16.h>
#include <mma.h>
#include <math.h>
#include <cstdint>

using namespace nvcuda;

#define N_TOK   8192
#define DMODEL  256
#define NEXP    16
#define NVIEW   3
#define TOPK    4
#define HDIM    1024
#define ASSIGN_TOTAL (NVIEW * N_TOK * TOPK)
#define CAP     ASSIGN_TOTAL
#define TPB     256
#define BM      32
#define NCHUNK  16
#define TPB4    256
#define TPB5    512

#define TILE_ELEMS 16384   /* 256x64 (or 64x256) fp16 per chunk */

/* dynamic SMEM layout (bytes) — 67072 total, 3 CTAs/SM */
#define XH_OFF  0                        /* X fp16 [32][264]  = 16896 */
#define W_OFF   16896                    /* 2 x 18432 cp.async ring   */
#define SLOT_BYTES 18432
#define H_OFF   53760                    /* H fp16 [32][72]   = 4608  */
#define SCR_OFF 58368                    /* fp32 scr [32][68] = 8704  */
#define SM_TOTAL 67072

/* aux kernel block ranges */
#define GBLK  192      /* gate blocks      */
#define WPB   512      /* wprep blocks     */
#define ZBLK  64       /* zero-out blocks  */
#define AUXB  (GBLK + WPB + ZBLK)

/* ------------- static device scratch ------------- */
__device__ __half g_w1[NEXP * NCHUNK * TILE_ELEMS];
__device__ __half g_w2[NEXP * NCHUNK * TILE_ELEMS];
__device__ int   g_cnt[NEXP];
__device__ int2  g_bucket[NEXP * CAP];

__device__ __forceinline__ uint32_t s2u(const void* p) {
    uint32_t a;
    asm("{ .reg .u64 t; cvta.to.shared.u64 t, %1; cvt.u32.u64 %0, t; }" : "=r"(a) : "l"(p));
    return a;
}
__device__ __forceinline__ float gelu_exact(float x) {
    return 0.5f * x * (1.0f + erff(x * 0.70710678118654752f));
}
__device__ __forceinline__ uint32_t f2h2(float a, float b) {
    __half2 h = __floats2half2_rn(a, b);
    return *(uint32_t*)&h;
}

/* ---------------- kernel 0: zero routing counters (16 ints) ------------- */
__global__ void prep_kernel() {
    if (threadIdx.x < NEXP) g_cnt[threadIdx.x] = 0;
}

/* ---------------- aux bodies: gate / wprep / zero ------------- */
__device__ void gate_body(int blk, const float* __restrict__ v0,
                          const float* __restrict__ v1, const float* __restrict__ v2,
                          const float* __restrict__ rw, const float* __restrict__ ek) {
    __shared__ float scomb[NEXP * DMODEL];
    __shared__ float skn2[NEXP];
    __shared__ int   scnt[NEXP];
    __shared__ int   sbase[NEXP];
    __shared__ int2  srec[TPB5];
    __shared__ int   sinfo[TPB5];

    int t = threadIdx.x, wid = t >> 5, lane = t & 31;
    int view = (blk * 128) >> 13;            /* uniform per block */
    {   /* compute combined router weights + |k|^2 in-block */
        const float* rwv = rw + view * NEXP * DMODEL;
        for (int i = t; i < NEXP * DMODEL; i += TPB5)
            scomb[i] = 2.0f * ek[i] + rwv[i];
        float s = 0.f;                        /* 16 warps -> 16 experts */
        #pragma unroll
        for (int j = 0; j < 8; j++) {
            float x = ek[wid * DMODEL + lane + 32 * j];
            s += x * x;
        }
        #pragma unroll
        for (int o = 16; o; o >>= 1) s += __shfl_xor_sync(0xffffffffu, s, o);
        if (lane == 0) { skn2[wid] = s; scnt[wid] = 0; }
    }
    __syncthreads();

    const float* vbase = (view == 0 ? v0 : (view == 1 ? v1 : v2));

    #pragma unroll 1
    for (int it = 0; it < 8; it++) {
        int wg  = blk * 128 + it * 16 + wid;
        int tok = wg & (N_TOK - 1);
        const float* vp = vbase + (size_t)tok * DMODEL;
        float xr[8];
        #pragma unroll
        for (int j = 0; j < 8; j++) xr[j] = vp[lane + 32 * j];
        float lg[NEXP];
        #pragma unroll
        for (int e = 0; e < NEXP; e++) {
            float p = 0.f;
            #pragma unroll
            for (int j = 0; j < 8; j++) p += xr[j] * scomb[e * DMODEL + lane + 32 * j];
            #pragma unroll
            for (int o = 16; o; o >>= 1) p += __shfl_xor_sync(0xffffffffu, p, o);
            lg[e] = p - skn2[e];
        }
        if (lane == 0) {
            float tv[TOPK]; int ti[TOPK]; unsigned used = 0;
            #pragma unroll
            for (int k = 0; k < TOPK; k++) {
                float best = -3.0e38f; int bi = 0;
                #pragma unroll
                for (int e = 0; e < NEXP; e++)
                    if (!((used >> e) & 1u) && lg[e] > best) { best = lg[e]; bi = e; }
                used |= 1u << bi; tv[k] = best; ti[k] = bi;
            }
            float mx = tv[0], ex[TOPK], s = 0.f;
            #pragma unroll
            for (int k = 0; k < TOPK; k++) { ex[k] = expf(tv[k] - mx); s += ex[k]; }
            float inv = 1.0f / s;
            int pid = (it * 16 + wid) * TOPK;
            #pragma unroll
            for (int k = 0; k < TOPK; k++) {
                int e = ti[k];
                int slot = atomicAdd(&scnt[e], 1);
                srec[pid + k]  = make_int2(wg, __float_as_int(ex[k] * inv));
                sinfo[pid + k] = (slot << 4) | e;
            }
        }
    }
    __syncthreads();
    if (t < NEXP) sbase[t] = atomicAdd(&g_cnt[t], scnt[t]);
    __syncthreads();
    {
        int info = sinfo[t];
        int e = info & 15, slot = info >> 4;
        g_bucket[(size_t)e * CAP + sbase[e] + slot] = srec[t];
    }
}

__device__ void wprep_body(int tile, const float* __restrict__ W1,
                           const float* __restrict__ W2) {
    int t = threadIdx.x;
    int e = tile >> 5, c = (tile >> 1) & 15, z = tile & 1;
    size_t base = (size_t)(e * NCHUNK + c) * TILE_ELEMS;
    if (z == 0) {
        const float* src = W1 + (size_t)e * 262144 + c * 64;
        uint2* dst = (uint2*)(g_w1 + base);
        for (int u = t; u < 4096; u += TPB5) {
            int k = u >> 4, n4 = u & 15;
            float4 f = *(const float4*)(src + (size_t)k * 1024 + n4 * 4);
            dst[u] = make_uint2(f2h2(f.x, f.y), f2h2(f.z, f.w));
        }
    } else {
        const float* src = W2 + (size_t)e * 262144 + (size_t)c * 64 * 256;
        uint2* dst = (uint2*)(g_w2 + base);
        for (int u = t; u < 4096; u += TPB5) {
            int k = u >> 6, n4 = u & 63;
            float4 f = *(const float4*)(src + (size_t)k * 256 + n4 * 4);
            dst[u] = make_uint2(f2h2(f.x, f.y), f2h2(f.z, f.w));
        }
    }
}

__device__ void zero_body(int b, float* __restrict__ out) {
    float4* o4 = (float4*)out;
    int i0 = b * 8192;
    #pragma unroll
    for (int j = 0; j < 16; j++)
        o4[i0 + j * TPB5 + threadIdx.x] = make_float4(0.f, 0.f, 0.f, 0.f);
}

/* ---------------- kernel 1: fused aux (gate || wprep || zero) ---------------- */
__global__ __launch_bounds__(TPB5) void aux_kernel(
    const float* __restrict__ v0, const float* __restrict__ v1,
    const float* __restrict__ v2,
    const float* __restrict__ rw, const float* __restrict__ ek,
    const float* __restrict__ W1, const float* __restrict__ W2,
    float* __restrict__ out)
{
    int blk = blockIdx.x;
    if (blk < GBLK)            gate_body(blk, v0, v1, v2, rw, ek);
    else if (blk < GBLK + WPB) wprep_body(blk - GBLK, W1, W2);
    else                       zero_body(blk - GBLK - WPB, out);
}

/* ------- kernel 2: fp16 WMMA grouped MLP, BM=32, 256 thr, 3 CTAs/SM ------- */
typedef wmma::fragment<wmma::matrix_a, 16, 16, 16, __half, wmma::row_major> FragA;
typedef wmma::fragment<wmma::matrix_b, 16, 16, 16, __half, wmma::row_major> FragB;
typedef wmma::fragment<wmma::accumulator, 16, 16, 16, float> FragC;

__device__ __forceinline__ void prefetch_phase(
    int p, int t, uint32_t smb, const __half* w1, const __half* w2)
{
    if (p < NCHUNK * 4) {
        int c = p >> 2, sub = p & 3;
        uint32_t slot = smb + W_OFF + (uint32_t)(p & 1) * SLOT_BYTES;
        if (sub < 2) {
            const char* src = (const char*)(w1 + ((size_t)c * 256 + sub * 128) * 64);
            #pragma unroll
            for (int v = 0; v < 4; v++) {
                int u = t + TPB4 * v;
                uint32_t dst = slot + (uint32_t)(u >> 3) * 144 + (uint32_t)(u & 7) * 16;
                asm volatile("cp.async.cg.shared.global [%0], [%1], 16;"
                             :: "r"(dst), "l"(src + (size_t)u * 16) : "memory");
            }
        } else {
            const char* src = (const char*)(w2 + ((size_t)c * 64 + (sub - 2) * 32) * 256);
            #pragma unroll
            for (int v = 0; v < 4; v++) {
                int u = t + TPB4 * v;
                uint32_t dst = slot + (uint32_t)(u >> 5) * 528 + (uint32_t)(u & 31) * 16;
                asm volatile("cp.async.cg.shared.global [%0], [%1], 16;"
                             :: "r"(dst), "l"(src + (size_t)u * 16) : "memory");
            }
        }
    }
    asm volatile("cp.async.commit_group;" ::: "memory");
}

#define SP_BEGIN(p) do {                                             \
    asm volatile("cp.async.wait_group 0;" ::: "memory");             \
    __syncthreads();                                                 \
    prefetch_phase((p) + 1, t, smb, w1, w2);                         \
} while (0)

__global__ __launch_bounds__(TPB4, 3)
void mlp_mma(const float* __restrict__ v0, const float* __restrict__ v1,
             const float* __restrict__ v2,
             const float* __restrict__ b1, const float* __restrict__ b2,
             float* __restrict__ out) {
    int e = blockIdx.y;
    int cnt = g_cnt[e];
    int r0 = blockIdx.x * BM;
    if (r0 >= cnt) return;

    extern __shared__ char dyn[];
    uint32_t smb = s2u(dyn);
    __half* Xh  = (__half*)(dyn + XH_OFF);          /* [32][264] */
    __half* Hh  = (__half*)(dyn + H_OFF);           /* [32][72]  */
    float*  scr = (float*)(dyn + SCR_OFF);          /* [32][68]  */

    __shared__ const float* s_ptr[BM];
    __shared__ float        s_gate[BM];
    __shared__ int          s_tok[BM];

    int t = threadIdx.x;
    const __half* w1 = g_w1 + (size_t)e * NCHUNK * TILE_ELEMS;
    const __half* w2 = g_w2 + (size_t)e * NCHUNK * TILE_ELEMS;

    prefetch_phase(0, t, smb, w1, w2);

    if (t < BM) {
        int gr = r0 + t;
        if (gr < cnt) {
            int2 rec = g_bucket[(size_t)e * CAP + gr];
            int view = rec.x >> 13, tok = rec.x & (N_TOK - 1);
            s_ptr[t] = (view == 0 ? v0 : (view == 1 ? v1 : v2)) + (size_t)tok * DMODEL;
            s_tok[t] = tok; s_gate[t] = __int_as_float(rec.y);
        } else { s_ptr[t] = v0; s_tok[t] = 0; s_gate[t] = 0.f; }
    }
    __syncthreads();

    /* stage X fp16: thread t -> row t>>3 (0..31), 32-col group t&7 */
    {
        int m = t >> 3, o = t & 7;
        const float4* src = (const float4*)(s_ptr[m] + o * 32);
        uint4* dst = (uint4*)&Xh[m * 264 + o * 32];
        #pragma unroll
        for (int v = 0; v < 4; v++) {
            float4 f0 = src[2 * v], f1 = src[2 * v + 1];
            dst[v] = make_uint4(f2h2(f0.x, f0.y), f2h2(f0.z, f0.w),
                                f2h2(f1.x, f1.y), f2h2(f1.z, f1.w));
        }
    }

    int wid = t >> 5;
    int wm = wid >> 2, wn = wid & 3;     /* 2x4 warp grid, 16-row tiles */

    FragC c2[4];
    #pragma unroll
    for (int n = 0; n < 4; n++) wmma::fill_fragment(c2[n], 0.0f);

    for (int c = 0; c < NCHUNK; c++) {
        int pb = c * 4;
        FragC c1;
        wmma::fill_fragment(c1, 0.0f);

        /* ---- GEMM1: C1[32][64] = X @ W1c, K=256 in 2 halves ---- */
        #pragma unroll
        for (int h = 0; h < 2; h++) {
            SP_BEGIN(pb + h);
            const __half* Ws = (const __half*)(dyn + W_OFF + ((pb + h) & 1) * SLOT_BYTES);
            #pragma unroll
            for (int ks = 0; ks < 8; ks++) {
                FragB b;
                wmma::load_matrix_sync(b, Ws + ks * 16 * 72 + wn * 16, 72);
                FragA a;
                wmma::load_matrix_sync(a, Xh + (wm * 16) * 264 + h * 128 + ks * 16, 264);
                wmma::mma_sync(c1, a, b, c1);
            }
        }

        /* ---- bias + gelu -> H fp16 ---- */
        wmma::store_matrix_sync(&scr[(wm * 16) * 68 + wn * 16], c1, 68, wmma::mem_row_major);
        __syncthreads();
        {
            int m = t >> 3, o = t & 7;
            const float* bb = b1 + e * HDIM + c * 64 + o * 8;
            uint32_t* dh = (uint32_t*)&Hh[m * 72 + o * 8];
            #pragma unroll
            for (int j = 0; j < 4; j++) {
                float g0 = gelu_exact(scr[m * 68 + o * 8 + 2 * j]     + __ldg(bb + 2 * j));
                float g1 = gelu_exact(scr[m * 68 + o * 8 + 2 * j + 1] + __ldg(bb + 2 * j + 1));
                dh[j] = f2h2(g0, g1);
            }
        }

        /* ---- GEMM2: C2[32][256] += H @ W2c, K=64 in 2 halves ---- */
        #pragma unroll
        for (int h = 0; h < 2; h++) {
            SP_BEGIN(pb + 2 + h);        /* sync also publishes Hh */
            const __half* Ws = (const __half*)(dyn + W_OFF + ((pb + 2 + h) & 1) * SLOT_BYTES);
            #pragma unroll
            for (int ks = 0; ks < 2; ks++) {
                FragA a;
                wmma::load_matrix_sync(a, Hh + (wm * 16) * 72 + h * 32 + ks * 16, 72);
                #pragma unroll
                for (int nf = 0; nf < 4; nf++) {
                    FragB b;
                    wmma::load_matrix_sync(b, Ws + ks * 16 * 264 + wn * 64 + nf * 16, 264);
                    wmma::mma_sync(c2[nf], a, b, c2[nf]);
                }
            }
        }
    }

    /* ---- epilogue: C2 -> out (gate, +b2) via scr in 4 column-quarters ---- */
    #pragma unroll
    for (int q = 0; q < 4; q++) {
        __syncthreads();
        if (wn == q) {
            #pragma unroll
            for (int nf = 0; nf < 4; nf++)
                wmma::store_matrix_sync(&scr[(wm * 16) * 68 + nf * 16],
                                        c2[nf], 68, wmma::mem_row_major);
        }
        __syncthreads();
        int m = t >> 3, o = t & 7;
        float g = s_gate[m];
        if (g != 0.f) {
            int tok = s_tok[m];
            int nbase = q * 64 + o * 8;
            #pragma unroll
            for (int j = 0; j < 8; j++) {
                int n = nbase + j;
                atomicAdd(&out[(size_t)tok * DMODEL + n],
                          g * (scr[m * 68 + o * 8 + j] + __ldg(&b2[e * DMODEL + n])));
            }
        }
    }
}

/* ---------------- launch ---------------- */
extern "C" void kernel_launch(void* const* d_in, const int* in_sizes, int n_in,
                              void* d_out, int out_size) {
    const float* v0 = (const float*)d_in[0];
    const float* v1 = (const float*)d_in[1];
    const float* v2 = (const float*)d_in[2];
    const float* rw = (const float*)d_in[3];
    const float* ek = (const float*)d_in[4];
    const float* W1 = (const float*)d_in[5];
    const float* b1 = (const float*)d_in[6];
    const float* W2 = (const float*)d_in[7];
    const float* b2 = (const float*)d_in[8];
    float* out = (float*)d_out;

    cudaFuncSetAttribute(mlp_mma, cudaFuncAttributeMaxDynamicSharedMemorySize, SM_TOTAL);

    prep_kernel<<<1, 32>>>();
    aux_kernel<<<AUXB, TPB5>>>(v0, v1, v2, rw, ek, W1, W2, out);

    dim3 grid(ASSIGN_TOTAL / BM, NEXP);
    mlp_mma<<<grid, TPB4, SM_TOTAL>>>(v0, v1, v2, b1, b2, out);
}

// round 12
// speedup vs baseline: 1.1261x; 1.1261x over previous
#include <cuda_runtime.h>
#include <cuda_fp16.h>
#include <mma.h>
#include <math.h>
#include <cstdint>

using namespace nvcuda;

#define N_TOK   8192
#define DMODEL  256
#define NEXP    16
#define NVIEW   3
#define TOPK    4
#define HDIM    1024
#define ASSIGN_TOTAL (NVIEW * N_TOK * TOPK)
#define CAP     ASSIGN_TOTAL
#define TPB     256
#define BM      64
#define NCHUNK  16
#define TPB4    256
#define TPB5    512
#define MAXTILES 1552     /* sum ceil(cnt_e/64) <= 1536 + 15 */

#define TILE_ELEMS 16384   /* 256x64 (or 64x256) fp16 per chunk */

/* dynamic SMEM layout (bytes) — 97280 total, 2 CTAs/SM (proven R9 config) */
#define XH_OFF  0                        /* X fp16 [64][264]  = 33792 */
#define W_OFF   33792                    /* 2 x 18432 cp.async ring   */
#define SLOT_BYTES 18432
#define H_OFF   70656                    /* H fp16 [64][72]   = 9216  */
#define SCR_OFF 79872                    /* fp32 scr [64][68] = 17408 */
#define SM_TOTAL 97280

/* aux kernel block ranges */
#define GBLK  192      /* gate blocks      */
#define WPB   512      /* wprep blocks     */
#define ZBLK  64       /* zero-out blocks  */
#define AUXB  (GBLK + WPB + ZBLK)

/* ------------- static device scratch ------------- */
__device__ __half g_w1[NEXP * NCHUNK * TILE_ELEMS];
__device__ __half g_w2[NEXP * NCHUNK * TILE_ELEMS];
__device__ int   g_cnt[NEXP];
__device__ int   g_tbase[NEXP + 1];     /* tile prefix sums */
__device__ int2  g_bucket[NEXP * CAP];

__device__ __forceinline__ uint32_t s2u(const void* p) {
    uint32_t a;
    asm("{ .reg .u64 t; cvta.to.shared.u64 t, %1; cvt.u32.u64 %0, t; }" : "=r"(a) : "l"(p));
    return a;
}
__device__ __forceinline__ float gelu_exact(float x) {
    return 0.5f * x * (1.0f + erff(x * 0.70710678118654752f));
}
__device__ __forceinline__ uint32_t f2h2(float a, float b) {
    __half2 h = __floats2half2_rn(a, b);
    return *(uint32_t*)&h;
}

/* ---------------- kernel 0: zero routing counters ------------- */
__global__ void prep_kernel() {
    if (threadIdx.x < NEXP) g_cnt[threadIdx.x] = 0;
}

/* ---------------- kernel 2: tile scheduler (prefix sums) ------------- */
__global__ void sched_kernel() {
    int t = threadIdx.x;                          /* 1 warp */
    int tiles = (t < NEXP) ? (g_cnt[t] + BM - 1) / BM : 0;
    int pre = tiles;
    #pragma unroll
    for (int o = 1; o < 32; o <<= 1) {
        int v = __shfl_up_sync(0xffffffffu, pre, o);
        if (t >= o) pre += v;
    }
    if (t < NEXP) g_tbase[t + 1] = pre;
    if (t == 0)  g_tbase[0] = 0;
}

/* ---------------- aux bodies: gate / wprep / zero ------------- */
__device__ void gate_body(int blk, const float* __restrict__ v0,
                          const float* __restrict__ v1, const float* __restrict__ v2,
                          const float* __restrict__ rw, const float* __restrict__ ek) {
    __shared__ float scomb[NEXP * DMODEL];
    __shared__ float skn2[NEXP];
    __shared__ int   scnt[NEXP];
    __shared__ int   sbase[NEXP];
    __shared__ int2  srec[TPB5];
    __shared__ int   sinfo[TPB5];

    int t = threadIdx.x, wid = t >> 5, lane = t & 31;
    int view = (blk * 128) >> 13;            /* uniform per block */
    {   /* combined router weights + |k|^2 computed in-block */
        const float* rwv = rw + view * NEXP * DMODEL;
        for (int i = t; i < NEXP * DMODEL; i += TPB5)
            scomb[i] = 2.0f * ek[i] + rwv[i];
        float s = 0.f;                        /* 16 warps -> 16 experts */
        #pragma unroll
        for (int j = 0; j < 8; j++) {
            float x = ek[wid * DMODEL + lane + 32 * j];
            s += x * x;
        }
        #pragma unroll
        for (int o = 16; o; o >>= 1) s += __shfl_xor_sync(0xffffffffu, s, o);
        if (lane == 0) { skn2[wid] = s; scnt[wid] = 0; }
    }
    __syncthreads();

    const float* vbase = (view == 0 ? v0 : (view == 1 ? v1 : v2));

    #pragma unroll 1
    for (int it = 0; it < 8; it++) {
        int wg  = blk * 128 + it * 16 + wid;
        int tok = wg & (N_TOK - 1);
        const float* vp = vbase + (size_t)tok * DMODEL;
        float xr[8];
        #pragma unroll
        for (int j = 0; j < 8; j++) xr[j] = vp[lane + 32 * j];
        float lg[NEXP];
        #pragma unroll
        for (int e = 0; e < NEXP; e++) {
            float p = 0.f;
            #pragma unroll
            for (int j = 0; j < 8; j++) p += xr[j] * scomb[e * DMODEL + lane + 32 * j];
            #pragma unroll
            for (int o = 16; o; o >>= 1) p += __shfl_xor_sync(0xffffffffu, p, o);
            lg[e] = p - skn2[e];
        }
        if (lane == 0) {
            float tv[TOPK]; int ti[TOPK]; unsigned used = 0;
            #pragma unroll
            for (int k = 0; k < TOPK; k++) {
                float best = -3.0e38f; int bi = 0;
                #pragma unroll
                for (int e = 0; e < NEXP; e++)
                    if (!((used >> e) & 1u) && lg[e] > best) { best = lg[e]; bi = e; }
                used |= 1u << bi; tv[k] = best; ti[k] = bi;
            }
            float mx = tv[0], ex[TOPK], s = 0.f;
            #pragma unroll
            for (int k = 0; k < TOPK; k++) { ex[k] = expf(tv[k] - mx); s += ex[k]; }
            float inv = 1.0f / s;
            int pid = (it * 16 + wid) * TOPK;
            #pragma unroll
            for (int k = 0; k < TOPK; k++) {
                int e = ti[k];
                int slot = atomicAdd(&scnt[e], 1);
                srec[pid + k]  = make_int2(wg, __float_as_int(ex[k] * inv));
                sinfo[pid + k] = (slot << 4) | e;
            }
        }
    }
    __syncthreads();
    if (t < NEXP) sbase[t] = atomicAdd(&g_cnt[t], scnt[t]);
    __syncthreads();
    {
        int info = sinfo[t];
        int e = info & 15, slot = info >> 4;
        g_bucket[(size_t)e * CAP + sbase[e] + slot] = srec[t];
    }
}

__device__ void wprep_body(int tile, const float* __restrict__ W1,
                           const float* __restrict__ W2) {
    int t = threadIdx.x;
    int e = tile >> 5, c = (tile >> 1) & 15, z = tile & 1;
    size_t base = (size_t)(e * NCHUNK + c) * TILE_ELEMS;
    if (z == 0) {
        const float* src = W1 + (size_t)e * 262144 + c * 64;
        uint2* dst = (uint2*)(g_w1 + base);
        for (int u = t; u < 4096; u += TPB5) {
            int k = u >> 4, n4 = u & 15;
            float4 f = *(const float4*)(src + (size_t)k * 1024 + n4 * 4);
            dst[u] = make_uint2(f2h2(f.x, f.y), f2h2(f.z, f.w));
        }
    } else {
        const float* src = W2 + (size_t)e * 262144 + (size_t)c * 64 * 256;
        uint2* dst = (uint2*)(g_w2 + base);
        for (int u = t; u < 4096; u += TPB5) {
            int k = u >> 6, n4 = u & 63;
            float4 f = *(const float4*)(src + (size_t)k * 256 + n4 * 4);
            dst[u] = make_uint2(f2h2(f.x, f.y), f2h2(f.z, f.w));
        }
    }
}

__device__ void zero_body(int b, float* __restrict__ out) {
    float4* o4 = (float4*)out;
    int i0 = b * 8192;
    #pragma unroll
    for (int j = 0; j < 16; j++)
        o4[i0 + j * TPB5 + threadIdx.x] = make_float4(0.f, 0.f, 0.f, 0.f);
}

/* ---------------- kernel 1: fused aux (gate || wprep || zero) ---------------- */
__global__ __launch_bounds__(TPB5) void aux_kernel(
    const float* __restrict__ v0, const float* __restrict__ v1,
    const float* __restrict__ v2,
    const float* __restrict__ rw, const float* __restrict__ ek,
    const float* __restrict__ W1, const float* __restrict__ W2,
    float* __restrict__ out)
{
    int blk = blockIdx.x;
    if (blk < GBLK)            gate_body(blk, v0, v1, v2, rw, ek);
    else if (blk < GBLK + WPB) wprep_body(blk - GBLK, W1, W2);
    else                       zero_body(blk - GBLK - WPB, out);
}

/* ------- kernel 3: fp16 WMMA grouped MLP, BM=64, 2 CTAs/SM, 1-D scheduled grid ---- */
typedef wmma::fragment<wmma::matrix_a, 16, 16, 16, __half, wmma::row_major> FragA;
typedef wmma::fragment<wmma::matrix_b, 16, 16, 16, __half, wmma::row_major> FragB;
typedef wmma::fragment<wmma::accumulator, 16, 16, 16, float> FragC;

__device__ __forceinline__ void prefetch_phase(
    int p, int t, uint32_t smb, const __half* w1, const __half* w2)
{
    if (p < NCHUNK * 4) {
        int c = p >> 2, sub = p & 3;
        uint32_t slot = smb + W_OFF + (uint32_t)(p & 1) * SLOT_BYTES;
        if (sub < 2) {
            const char* src = (const char*)(w1 + ((size_t)c * 256 + sub * 128) * 64);
            #pragma unroll
            for (int v = 0; v < 4; v++) {
                int u = t + TPB4 * v;
                uint32_t dst = slot + (uint32_t)(u >> 3) * 144 + (uint32_t)(u & 7) * 16;
                asm volatile("cp.async.cg.shared.global [%0], [%1], 16;"
                             :: "r"(dst), "l"(src + (size_t)u * 16) : "memory");
            }
        } else {
            const char* src = (const char*)(w2 + ((size_t)c * 64 + (sub - 2) * 32) * 256);
            #pragma unroll
            for (int v = 0; v < 4; v++) {
                int u = t + TPB4 * v;
                uint32_t dst = slot + (uint32_t)(u >> 5) * 528 + (uint32_t)(u & 31) * 16;
                asm volatile("cp.async.cg.shared.global [%0], [%1], 16;"
                             :: "r"(dst), "l"(src + (size_t)u * 16) : "memory");
            }
        }
    }
    asm volatile("cp.async.commit_group;" ::: "memory");
}

#define SP_BEGIN(p) do {                                             \
    asm volatile("cp.async.wait_group 0;" ::: "memory");             \
    __syncthreads();                                                 \
    prefetch_phase((p) + 1, t, smb, w1, w2);                         \
} while (0)

__global__ __launch_bounds__(TPB4, 2)
void mlp_mma(const float* __restrict__ v0, const float* __restrict__ v1,
             const float* __restrict__ v2,
             const float* __restrict__ b1, const float* __restrict__ b2,
             float* __restrict__ out) {
    __shared__ int s_pre[NEXP + 1];
    int t = threadIdx.x;
    if (t < NEXP + 1) s_pre[t] = g_tbase[t];
    __syncthreads();
    int bid = blockIdx.x;
    if (bid >= s_pre[NEXP]) return;
    int e = 0;
    #pragma unroll
    for (int i = 1; i < NEXP; i++) e += (bid >= s_pre[i]);
    int r0 = (bid - s_pre[e]) * BM;
    int cnt = g_cnt[e];

    extern __shared__ char dyn[];
    uint32_t smb = s2u(dyn);
    __half* Xh  = (__half*)(dyn + XH_OFF);
    __half* Hh  = (__half*)(dyn + H_OFF);
    float*  scr = (float*)(dyn + SCR_OFF);

    __shared__ const float* s_ptr[BM];
    __shared__ float        s_gate[BM];
    __shared__ int          s_tok[BM];

    const __half* w1 = g_w1 + (size_t)e * NCHUNK * TILE_ELEMS;
    const __half* w2 = g_w2 + (size_t)e * NCHUNK * TILE_ELEMS;

    prefetch_phase(0, t, smb, w1, w2);

    if (t < BM) {
        int gr = r0 + t;
        if (gr < cnt) {
            int2 rec = g_bucket[(size_t)e * CAP + gr];
            int view = rec.x >> 13, tok = rec.x & (N_TOK - 1);
            s_ptr[t] = (view == 0 ? v0 : (view == 1 ? v1 : v2)) + (size_t)tok * DMODEL;
            s_tok[t] = tok; s_gate[t] = __int_as_float(rec.y);
        } else { s_ptr[t] = v0; s_tok[t] = 0; s_gate[t] = 0.f; }
    }
    __syncthreads();

    /* stage X fp16: thread t -> row t>>2 (0..63), 64-col quarter t&3 */
    {
        int m = t >> 2, q = t & 3;
        const float4* src = (const float4*)(s_ptr[m] + q * 64);
        uint32_t* dh = (uint32_t*)&Xh[m * 264 + q * 64];
        #pragma unroll
        for (int j = 0; j < 16; j++) {
            float4 f = src[j];
            dh[2 * j]     = f2h2(f.x, f.y);
            dh[2 * j + 1] = f2h2(f.z, f.w);
        }
    }

    int wid = t >> 5;
    int wm = wid >> 2, wn = wid & 3;     /* 2x4 warp grid */

    FragC c2[2][4];
    #pragma unroll
    for (int i = 0; i < 2; i++)
        #pragma unroll
        for (int n = 0; n < 4; n++) wmma::fill_fragment(c2[i][n], 0.0f);

    for (int c = 0; c < NCHUNK; c++) {
        int pb = c * 4;
        FragC c1[2];
        wmma::fill_fragment(c1[0], 0.0f);
        wmma::fill_fragment(c1[1], 0.0f);

        /* ---- GEMM1: C1[64][64] = X @ W1c, K=256 in 2 halves ---- */
        #pragma unroll
        for (int h = 0; h < 2; h++) {
            SP_BEGIN(pb + h);
            const __half* Ws = (const __half*)(dyn + W_OFF + ((pb + h) & 1) * SLOT_BYTES);
            #pragma unroll
            for (int ks = 0; ks < 8; ks++) {
                FragB b;
                wmma::load_matrix_sync(b, Ws + ks * 16 * 72 + wn * 16, 72);
                #pragma unroll
                for (int i = 0; i < 2; i++) {
                    FragA a;
                    wmma::load_matrix_sync(a, Xh + (wm * 32 + i * 16) * 264 + h * 128 + ks * 16, 264);
                    wmma::mma_sync(c1[i], a, b, c1[i]);
                }
            }
        }

        /* ---- bias + gelu -> H fp16 ---- */
        wmma::store_matrix_sync(&scr[(wm * 32) * 68 + wn * 16], c1[0], 68, wmma::mem_row_major);
        wmma::store_matrix_sync(&scr[(wm * 32 + 16) * 68 + wn * 16], c1[1], 68, wmma::mem_row_major);
        __syncthreads();
        {
            int m = t >> 2, q = t & 3;
            const float* bb = b1 + e * HDIM + c * 64 + q * 16;
            uint32_t* dh = (uint32_t*)&Hh[m * 72 + q * 16];
            #pragma unroll
            for (int j = 0; j < 8; j++) {
                float g0 = gelu_exact(scr[m * 68 + q * 16 + 2 * j]     + __ldg(bb + 2 * j));
                float g1 = gelu_exact(scr[m * 68 + q * 16 + 2 * j + 1] + __ldg(bb + 2 * j + 1));
                dh[j] = f2h2(g0, g1);
            }
        }

        /* ---- GEMM2: C2[64][256] += H @ W2c, K=64 in 2 halves ---- */
        #pragma unroll
        for (int h = 0; h < 2; h++) {
            SP_BEGIN(pb + 2 + h);        /* sync also publishes Hh */
            const __half* Ws = (const __half*)(dyn + W_OFF + ((pb + 2 + h) & 1) * SLOT_BYTES);
            #pragma unroll
            for (int ks = 0; ks < 2; ks++) {
                #pragma unroll
                for (int i = 0; i < 2; i++) {
                    FragA a;
                    wmma::load_matrix_sync(a, Hh + (wm * 32 + i * 16) * 72 + h * 32 + ks * 16, 72);
                    #pragma unroll
                    for (int nf = 0; nf < 4; nf++) {
                        FragB b;
                        wmma::load_matrix_sync(b, Ws + ks * 16 * 264 + wn * 64 + nf * 16, 264);
                        wmma::mma_sync(c2[i][nf], a, b, c2[i][nf]);
                    }
                }
            }
        }
    }

    /* ---- epilogue: C2 -> out (gate, +b2) via scr in 4 column-quarters ---- */
    #pragma unroll
    for (int q = 0; q < 4; q++) {
        __syncthreads();
        if (wn == q) {
            #pragma unroll
            for (int i = 0; i < 2; i++)
                #pragma unroll
                for (int nf = 0; nf < 4; nf++)
                    wmma::store_matrix_sync(&scr[(wm * 32 + i * 16) * 68 + nf * 16],
                                            c2[i][nf], 68, wmma::mem_row_major);
        }
        __syncthreads();
        int m = t >> 2, cq = t & 3;
        float g = s_gate[m];
        if (g != 0.f) {
            int tok = s_tok[m];
            int nbase = q * 64 + cq * 16;
            #pragma unroll
            for (int j = 0; j < 16; j++) {
                int n = nbase + j;
                atomicAdd(&out[(size_t)tok * DMODEL + n],
                          g * (scr[m * 68 + cq * 16 + j] + __ldg(&b2[e * DMODEL + n])));
            }
        }
    }
}

/* ---------------- launch ---------------- */
extern "C" void kernel_launch(void* const* d_in, const int* in_sizes, int n_in,
                              void* d_out, int out_size) {
    const float* v0 = (const float*)d_in[0];
    const float* v1 = (const float*)d_in[1];
    const float* v2 = (const float*)d_in[2];
    const float* rw = (const float*)d_in[3];
    const float* ek = (const float*)d_in[4];
    const float* W1 = (const float*)d_in[5];
    const float* b1 = (const float*)d_in[6];
    const float* W2 = (const float*)d_in[7];
    const float* b2 = (const float*)d_in[8];
    float* out = (float*)d_out;

    cudaFuncSetAttribute(mlp_mma, cudaFuncAttributeMaxDynamicSharedMemorySize, SM_TOTAL);

    prep_kernel<<<1, 32>>>();
    aux_kernel<<<AUXB, TPB5>>>(v0, v1, v2, rw, ek, W1, W2, out);
    sched_kernel<<<1, 32>>>();
    mlp_mma<<<MAXTILES, TPB4, SM_TOTAL>>>(v0, v1, v2, b1, b2, out);
}